// round 5
// baseline (speedup 1.0000x reference)
#include <cuda_runtime.h>
#include <math.h>

// Problem constants
#define B      512
#define H      512
#define KDIM   512
#define TENC   512
#define TDEC   128

// GEMM tiling
#define BM       64     // batch rows per CTA
#define JHT      32     // hidden columns per CTA
#define BN       128    // 4 gates * JHT z-columns per CTA
#define KC       16     // K chunk
#define NT       (KDIM / KC)
#define NTHREADS 256

// Persistent state (no allocation allowed)
__device__ float g_h0[B * H];
__device__ float g_h1[B * H];
__device__ float g_c[B * H];
__device__ float g_x[B];

__device__ __forceinline__ float sigf(float x) {
    return 1.0f / (1.0f + __expf(-x));
}

// Zero h0 and c.
__global__ void zero_state_kernel() {
    int i = blockIdx.x * blockDim.x + threadIdx.x;
    if (i < B * H) { g_h0[i] = 0.0f; g_c[i] = 0.0f; }
}

// Seed decoder input x0 = inputs[:, TENC-1, 0]
__global__ void seed_x_kernel(const float* __restrict__ inputs) {
    int b = blockIdx.x * blockDim.x + threadIdx.x;
    if (b < B) g_x[b] = inputs[b * TENC + (TENC - 1)];
}

// One fused LSTM step:
//   z[b, n] = sum_k h_in[b,k] * W[n,k] + x[b]*Wih[n] + bias[n],  n in [0,2048)
//   gates i,f,g,o = z[:, 0:512], [512:1024], [1024:1536], [1536:2048]
//   c = sig(f)*c + sig(i)*tanh(g);  h_out = sig(o)*tanh(c)
// CTA computes batch tile [by*64, by*64+64) x hidden tile [bx*32, bx*32+32),
// i.e. 128 z-columns (4 gates x 32).
__global__ void __launch_bounds__(NTHREADS)
lstm_step_kernel(const float* __restrict__ h_in,
                 float*       __restrict__ h_out,
                 const float* __restrict__ W,     // (2048, 512) row-major
                 const float* __restrict__ Wih,   // (2048)
                 const float* __restrict__ bias,  // (2048)
                 const float* __restrict__ x_base,
                 int x_stride, int x_off)
{
    // 32 KB pool: GEMM staging (As 8KB + Bs 16KB), then reused as zs (32KB).
    __shared__ float pool[8192];
    float* As = pool;          // [2][KC][BM]  = 2048 floats
    float* Bs = pool + 2048;   // [2][KC][BN]  = 4096 floats
    float* zs = pool;          // [BM][BN]     = 8192 floats (after compute)

    const int tid     = threadIdx.x;
    const int bx      = blockIdx.x;       // hidden tile: 0..15
    const int by      = blockIdx.y;       // batch  tile: 0..7
    const int jh_base = bx * JHT;
    const int brow0   = by * BM;

    // A (h) load mapping: one float4 per thread per chunk
    const int am = tid >> 2;              // 0..63   (batch row within tile)
    const int ak = (tid & 3) * 4;         // 0,4,8,12
    const float* aptr = h_in + (size_t)(brow0 + am) * KDIM + ak;

    // B (W) load mapping: two float4 per thread per chunk
    const int bn = tid >> 1;              // 0..127  (z-column within tile)
    const int bk = (tid & 1) * 8;         // 0 or 8
    const int wrow = (bn >> 5) * H + jh_base + (bn & 31);  // gate*512 + jh
    const float* bptr = W + (size_t)wrow * KDIM + bk;

    const int tx = tid & 15;
    const int ty = tid >> 4;

    float acc[4][8];
#pragma unroll
    for (int i = 0; i < 4; i++)
#pragma unroll
        for (int j = 0; j < 8; j++) acc[i][j] = 0.0f;

    // Preload chunk 0 into buffer 0
    {
        float4 av  = *(const float4*)(aptr);
        As[(ak + 0) * BM + am] = av.x;
        As[(ak + 1) * BM + am] = av.y;
        As[(ak + 2) * BM + am] = av.z;
        As[(ak + 3) * BM + am] = av.w;
        float4 bv0 = *(const float4*)(bptr);
        float4 bv1 = *(const float4*)(bptr + 4);
        Bs[(bk + 0) * BN + bn] = bv0.x;
        Bs[(bk + 1) * BN + bn] = bv0.y;
        Bs[(bk + 2) * BN + bn] = bv0.z;
        Bs[(bk + 3) * BN + bn] = bv0.w;
        Bs[(bk + 4) * BN + bn] = bv1.x;
        Bs[(bk + 5) * BN + bn] = bv1.y;
        Bs[(bk + 6) * BN + bn] = bv1.z;
        Bs[(bk + 7) * BN + bn] = bv1.w;
    }
    __syncthreads();

    for (int kt = 0; kt < NT; kt++) {
        const int buf = kt & 1;

        // Prefetch next chunk into registers (overlaps with compute)
        float4 av, bv0, bv1;
        if (kt + 1 < NT) {
            const float* ap = aptr + (kt + 1) * KC;
            av  = *(const float4*)(ap);
            const float* bp = bptr + (kt + 1) * KC;
            bv0 = *(const float4*)(bp);
            bv1 = *(const float4*)(bp + 4);
        }

        const float* Asb = As + buf * (KC * BM);
        const float* Bsb = Bs + buf * (KC * BN);
#pragma unroll
        for (int kk = 0; kk < KC; kk++) {
            float4 a4  = *(const float4*)(Asb + kk * BM + ty * 4);
            float4 b4a = *(const float4*)(Bsb + kk * BN + tx * 8);
            float4 b4b = *(const float4*)(Bsb + kk * BN + tx * 8 + 4);
            float a[4] = {a4.x, a4.y, a4.z, a4.w};
            float bb[8] = {b4a.x, b4a.y, b4a.z, b4a.w,
                           b4b.x, b4b.y, b4b.z, b4b.w};
#pragma unroll
            for (int i = 0; i < 4; i++)
#pragma unroll
                for (int j = 0; j < 8; j++)
                    acc[i][j] = fmaf(a[i], bb[j], acc[i][j]);
        }

        if (kt + 1 < NT) {
            const int nb = buf ^ 1;
            float* Asn = As + nb * (KC * BM);
            float* Bsn = Bs + nb * (KC * BN);
            Asn[(ak + 0) * BM + am] = av.x;
            Asn[(ak + 1) * BM + am] = av.y;
            Asn[(ak + 2) * BM + am] = av.z;
            Asn[(ak + 3) * BM + am] = av.w;
            Bsn[(bk + 0) * BN + bn] = bv0.x;
            Bsn[(bk + 1) * BN + bn] = bv0.y;
            Bsn[(bk + 2) * BN + bn] = bv0.z;
            Bsn[(bk + 3) * BN + bn] = bv0.w;
            Bsn[(bk + 4) * BN + bn] = bv1.x;
            Bsn[(bk + 5) * BN + bn] = bv1.y;
            Bsn[(bk + 6) * BN + bn] = bv1.z;
            Bsn[(bk + 7) * BN + bn] = bv1.w;
        }
        __syncthreads();
    }

    // Stage z tile to smem (staging buffers no longer needed; synced above)
#pragma unroll
    for (int i = 0; i < 4; i++) {
        const int row = ty * 4 + i;
        *(float4*)(zs + row * BN + tx * 8) =
            make_float4(acc[i][0], acc[i][1], acc[i][2], acc[i][3]);
        *(float4*)(zs + row * BN + tx * 8 + 4) =
            make_float4(acc[i][4], acc[i][5], acc[i][6], acc[i][7]);
    }
    __syncthreads();

    // Gate pass: each thread handles 8 (b, jh) pairs
    const int jl = tid & 31;
    const int m0 = tid >> 5;   // 0..7
    const int jh = jh_base + jl;
    const float wi0 = Wih[jh],         bv0e = bias[jh];
    const float wi1 = Wih[H + jh],     bv1e = bias[H + jh];
    const float wi2 = Wih[2 * H + jh], bv2e = bias[2 * H + jh];
    const float wi3 = Wih[3 * H + jh], bv3e = bias[3 * H + jh];

#pragma unroll
    for (int mm = 0; mm < 8; mm++) {
        const int m = m0 + mm * 8;
        const int b = brow0 + m;
        const float xv = x_base[b * x_stride + x_off];
        const float zi = zs[m * BN + jl]       + xv * wi0 + bv0e;
        const float zf = zs[m * BN + 32 + jl]  + xv * wi1 + bv1e;
        const float zg = zs[m * BN + 64 + jl]  + xv * wi2 + bv2e;
        const float zo = zs[m * BN + 96 + jl]  + xv * wi3 + bv3e;
        const int idx = b * H + jh;
        const float co = g_c[idx];
        const float cn = sigf(zf) * co + sigf(zi) * tanhf(zg);
        g_c[idx]   = cn;
        h_out[idx] = sigf(zo) * tanhf(cn);
    }
}

// Decoder output: out[b] = h[b,:] . linW + linb; also feeds back as next x.
__global__ void __launch_bounds__(256)
dec_out_kernel(const float* __restrict__ h,
               const float* __restrict__ linW,
               const float* __restrict__ linb,
               float* __restrict__ out, int t)
{
    const int b    = blockIdx.x * 8 + (threadIdx.x >> 5);
    const int lane = threadIdx.x & 31;
    const float* hr = h + (size_t)b * H;
    float s = 0.0f;
#pragma unroll
    for (int k = lane; k < H; k += 32)
        s = fmaf(hr[k], linW[k], s);
#pragma unroll
    for (int o = 16; o; o >>= 1)
        s += __shfl_xor_sync(0xffffffffu, s, o);
    if (lane == 0) {
        const float v = s + linb[0];
        g_x[b] = v;
        out[b * TDEC + t] = v;
    }
}

extern "C" void kernel_launch(void* const* d_in, const int* in_sizes, int n_in,
                              void* d_out, int out_size)
{
    (void)in_sizes; (void)n_in; (void)out_size;
    const float* inputs  = (const float*)d_in[0];
    // d_in[1] = targets (unused: teacher_forcing_ratio == 0)
    const float* encWih  = (const float*)d_in[2];
    const float* encWhh  = (const float*)d_in[3];
    const float* encB    = (const float*)d_in[4];
    const float* decWih  = (const float*)d_in[5];
    const float* decWhh  = (const float*)d_in[6];
    const float* decB    = (const float*)d_in[7];
    const float* linW    = (const float*)d_in[8];
    const float* linB    = (const float*)d_in[9];
    float* out = (float*)d_out;

    float *h0p, *h1p, *xp;
    cudaGetSymbolAddress((void**)&h0p, g_h0);
    cudaGetSymbolAddress((void**)&h1p, g_h1);
    cudaGetSymbolAddress((void**)&xp,  g_x);
    float* hb[2] = {h0p, h1p};

    const dim3 grid(H / JHT, B / BM);   // (16, 8) = 128 CTAs

    zero_state_kernel<<<(B * H + 255) / 256, 256>>>();

    int s = 0;
    for (int t = 0; t < TENC; t++, s++) {
        lstm_step_kernel<<<grid, NTHREADS>>>(
            hb[s & 1], hb[(s & 1) ^ 1], encWhh, encWih, encB,
            inputs, TENC, t);
    }

    seed_x_kernel<<<2, 256>>>(inputs);

    for (int t = 0; t < TDEC; t++, s++) {
        lstm_step_kernel<<<grid, NTHREADS>>>(
            hb[s & 1], hb[(s & 1) ^ 1], decWhh, decWih, decB,
            xp, 1, 0);
        dec_out_kernel<<<B / 8, 256>>>(hb[(s & 1) ^ 1], linW, linB, out, t);
    }
}

// round 7
// speedup vs baseline: 1.7942x; 1.7942x over previous
#include <cuda_runtime.h>
#include <cuda_bf16.h>
#include <stdint.h>
#include <math.h>

#define B      512
#define H      512
#define TENC   512
#define TDEC   128
#define NTHREADS 256
#define NCHUNK 24                    // 3 split-parts * (512/64) K-chunks
#define SMEM_DYN (49152 + 1024)      // A(16K)+B(8K) x2 buffers + align slack

// ---------------- persistent device state (no allocation allowed) ----------
static __device__ __align__(16) __nv_bfloat16 g_hhi0[B * H];
static __device__ __align__(16) __nv_bfloat16 g_hhi1[B * H];
static __device__ __align__(16) __nv_bfloat16 g_hlo0[B * H];
static __device__ __align__(16) __nv_bfloat16 g_hlo1[B * H];
static __device__ float g_c[B * H];
static __device__ float g_x[B];
static __device__ __align__(16) __nv_bfloat16 g_whi_e[2048 * 512];
static __device__ __align__(16) __nv_bfloat16 g_wlo_e[2048 * 512];
static __device__ __align__(16) __nv_bfloat16 g_whi_d[2048 * 512];
static __device__ __align__(16) __nv_bfloat16 g_wlo_d[2048 * 512];

// ---------------- helpers ----------------------------------------------------
__device__ __forceinline__ uint32_t smem_u32(const void* p) {
    uint32_t a;
    asm("{ .reg .u64 t; cvta.to.shared.u64 t, %1; cvt.u32.u64 %0, t; }"
        : "=r"(a) : "l"(p));
    return a;
}

__device__ __forceinline__ void ldsm_x4(uint32_t& r0, uint32_t& r1,
                                        uint32_t& r2, uint32_t& r3,
                                        uint32_t addr) {
    asm volatile("ldmatrix.sync.aligned.m8n8.x4.shared.b16 {%0,%1,%2,%3}, [%4];"
                 : "=r"(r0), "=r"(r1), "=r"(r2), "=r"(r3) : "r"(addr));
}

__device__ __forceinline__ void mma_bf16(float* c, const uint32_t* a,
                                         uint32_t b0, uint32_t b1) {
    asm volatile(
        "mma.sync.aligned.m16n8k16.row.col.f32.bf16.bf16.f32 "
        "{%0,%1,%2,%3}, {%4,%5,%6,%7}, {%8,%9}, {%0,%1,%2,%3};"
        : "+f"(c[0]), "+f"(c[1]), "+f"(c[2]), "+f"(c[3])
        : "r"(a[0]), "r"(a[1]), "r"(a[2]), "r"(a[3]), "r"(b0), "r"(b1));
}

__device__ __forceinline__ float sigf(float x) {
    return 1.0f / (1.0f + __expf(-x));
}

// ---------------- prologue kernels -------------------------------------------
// Repack W (2048,512): packed row n' = nt*64 + g*16 + jl  <->  n = g*512 + nt*16 + jl
__global__ void pack_w_kernel(const float* __restrict__ W,
                              __nv_bfloat16* __restrict__ whi,
                              __nv_bfloat16* __restrict__ wlo) {
    int idx = blockIdx.x * 256 + threadIdx.x;    // n'*512 + k
    int np = idx >> 9, k = idx & 511;
    int nt = np >> 6, r = np & 63;
    int n = (r >> 4) * 512 + nt * 16 + (r & 15);
    float w = W[n * 512 + k];
    __nv_bfloat16 hi = __float2bfloat16_rn(w);
    whi[idx] = hi;
    wlo[idx] = __float2bfloat16_rn(w - __bfloat162float(hi));
}

__global__ void zero_state_kernel() {
    int i = blockIdx.x * 256 + threadIdx.x;
    if (i < B * H) {
        g_hhi0[i] = __float2bfloat16(0.0f);
        g_hlo0[i] = __float2bfloat16(0.0f);
        g_c[i] = 0.0f;
    }
}

__global__ void seed_x_kernel(const float* __restrict__ inputs) {
    int b = blockIdx.x * 256 + threadIdx.x;
    if (b < B) g_x[b] = inputs[b * TENC + (TENC - 1)];
}

// ---------------- fused LSTM step (HMMA mma.sync) ----------------------------
// CTA (nt, mt): batch rows [mt*128,+128), packed z-cols [nt*64,+64)
// (= 4 gates x 16 hidden units jh in [nt*16,+16)).
// Split-3 bf16: hh*Wh + hh*Wl + hl*Wh as one K=1536 accumulation.
__global__ void __launch_bounds__(NTHREADS, 1)
lstm_step_kernel(const __nv_bfloat16* __restrict__ hhi,
                 const __nv_bfloat16* __restrict__ hlo,
                 __nv_bfloat16* __restrict__ hhi_out,
                 __nv_bfloat16* __restrict__ hlo_out,
                 const __nv_bfloat16* __restrict__ whi,
                 const __nv_bfloat16* __restrict__ wlo,
                 const float* __restrict__ Wih,
                 const float* __restrict__ bias,
                 const float* __restrict__ x_base,
                 int x_stride, int x_off)
{
    extern __shared__ char dsmem[];
    uint32_t raw = smem_u32(dsmem);
    uint32_t sb  = (raw + 1023) & ~1023u;
    char* sp     = dsmem + (sb - raw);
    // A: 128x64 bf16 (16KB), B: 64x64 bf16 (8KB), double buffered
    char*    aP[2] = { sp,          sp + 24576 };
    char*    bP[2] = { sp + 16384,  sp + 40960 };
    uint32_t aU[2] = { sb,          sb + 24576 };
    uint32_t bU[2] = { sb + 16384,  sb + 40960 };
    float*   zs    = (float*)sp;     // 128 x 68 f32 (34.8KB), after GEMM

    const int tid  = threadIdx.x;
    const int wid  = tid >> 5;
    const int lane = tid & 31;
    const int wm   = wid >> 1;        // warp m-tile 0..3 (32 rows each)
    const int wn   = wid & 1;         // warp n-tile 0..1 (32 cols each)
    const int nt   = blockIdx.x;      // 0..31
    const int mt   = blockIdx.y;      // 0..3
    const int brow0 = mt * 128;

    // ---- global->smem staging mapping (16B per slot, SW128 swizzle) -------
    const int gr  = tid >> 3;                 // 0..31 (row step 32)
    const int gce = (tid & 7) * 8;            // element col (8 bf16 = 16B)
    uint32_t soA[4], soB[2];
#pragma unroll
    for (int i = 0; i < 4; i++) {
        int row = gr + 32 * i;
        soA[i] = (uint32_t)row * 128u + (((uint32_t)gce * 2) ^ (uint32_t)((row & 7) << 4));
    }
#pragma unroll
    for (int i = 0; i < 2; i++) {
        int row = gr + 32 * i;
        soB[i] = (uint32_t)row * 128u + (((uint32_t)gce * 2) ^ (uint32_t)((row & 7) << 4));
    }

    // ---- ldmatrix lane addressing (per warp) -------------------------------
    const int lrow = lane & 15;
    const uint32_t kb2 = (uint32_t)((lane >> 4) * 16);   // byte offset of k-half
    uint32_t aoff[2], axor[2], boff[2], bxor[2];
#pragma unroll
    for (int mi = 0; mi < 2; mi++) {
        int r = wm * 32 + mi * 16 + lrow;
        aoff[mi] = (uint32_t)r * 128u;
        axor[mi] = (uint32_t)((r & 7) << 4);
    }
#pragma unroll
    for (int nb = 0; nb < 2; nb++) {
        int r = wn * 32 + nb * 16 + lrow;
        boff[nb] = (uint32_t)r * 128u;
        bxor[nb] = (uint32_t)((r & 7) << 4);
    }

    float acc[2][4][4];
#pragma unroll
    for (int mi = 0; mi < 2; mi++)
#pragma unroll
        for (int ni = 0; ni < 4; ni++)
#pragma unroll
            for (int q = 0; q < 4; q++) acc[mi][ni][q] = 0.0f;

    // ---- preload chunk 0 ----------------------------------------------------
    {
        const __nv_bfloat16* aS = hhi;
        const __nv_bfloat16* bS = whi;
#pragma unroll
        for (int i = 0; i < 4; i++)
            *(uint4*)(aP[0] + soA[i]) =
                *(const uint4*)(aS + (size_t)(brow0 + gr + 32 * i) * 512 + gce);
#pragma unroll
        for (int i = 0; i < 2; i++)
            *(uint4*)(bP[0] + soB[i]) =
                *(const uint4*)(bS + (size_t)(nt * 64 + gr + 32 * i) * 512 + gce);
    }
    __syncthreads();

    // ---- main K loop --------------------------------------------------------
    for (int k = 0; k < NCHUNK; k++) {
        const int bsel = k & 1;

        // prefetch next chunk into registers
        uint4 ra[4], rb[2];
        if (k + 1 < NCHUNK) {
            const int kn   = k + 1;
            const int part = kn >> 3;
            const int koff = (kn & 7) * 64;
            const __nv_bfloat16* aS = (part < 2 ? hhi : hlo);
            const __nv_bfloat16* bS = (part == 1 ? wlo : whi);
#pragma unroll
            for (int i = 0; i < 4; i++)
                ra[i] = *(const uint4*)(aS + (size_t)(brow0 + gr + 32 * i) * 512 + koff + gce);
#pragma unroll
            for (int i = 0; i < 2; i++)
                rb[i] = *(const uint4*)(bS + (size_t)(nt * 64 + gr + 32 * i) * 512 + koff + gce);
        }

        // compute current chunk: 4 k16 steps
        const uint32_t au = aU[bsel];
        const uint32_t bu = bU[bsel];
#pragma unroll
        for (int s = 0; s < 4; s++) {
            const uint32_t kb = (uint32_t)(s * 32);    // k0*2 bytes
            uint32_t af[2][4];
#pragma unroll
            for (int mi = 0; mi < 2; mi++)
                ldsm_x4(af[mi][0], af[mi][1], af[mi][2], af[mi][3],
                        au + aoff[mi] + ((kb + kb2) ^ axor[mi]));
            uint32_t bq[4][2];
#pragma unroll
            for (int nb = 0; nb < 2; nb++) {
                uint32_t q0, q1, q2, q3;
                ldsm_x4(q0, q1, q2, q3,
                        bu + boff[nb] + ((kb + kb2) ^ bxor[nb]));
                bq[nb * 2 + 0][0] = q0; bq[nb * 2 + 0][1] = q2;
                bq[nb * 2 + 1][0] = q1; bq[nb * 2 + 1][1] = q3;
            }
#pragma unroll
            for (int mi = 0; mi < 2; mi++)
#pragma unroll
                for (int ni = 0; ni < 4; ni++)
                    mma_bf16(acc[mi][ni], af[mi], bq[ni][0], bq[ni][1]);
        }

        // stage prefetched chunk into the other buffer
        if (k + 1 < NCHUNK) {
            char* ad = aP[bsel ^ 1];
            char* bd = bP[bsel ^ 1];
#pragma unroll
            for (int i = 0; i < 4; i++) *(uint4*)(ad + soA[i]) = ra[i];
#pragma unroll
            for (int i = 0; i < 2; i++) *(uint4*)(bd + soB[i]) = rb[i];
        }
        __syncthreads();
    }

    // ---- accum -> smem z tile (stride 68 to dodge bank conflicts) ----------
    {
        const int g  = lane >> 2;
        const int t2 = (lane & 3) * 2;
#pragma unroll
        for (int mi = 0; mi < 2; mi++)
#pragma unroll
            for (int ni = 0; ni < 4; ni++) {
                const int row = wm * 32 + mi * 16 + g;
                const int col = wn * 32 + ni * 8 + t2;
                *(float2*)(zs + row * 68 + col) =
                    make_float2(acc[mi][ni][0], acc[mi][ni][1]);
                *(float2*)(zs + (row + 8) * 68 + col) =
                    make_float2(acc[mi][ni][2], acc[mi][ni][3]);
            }
    }
    __syncthreads();

    // ---- gate pass: thread handles 8 (b, jh) pairs --------------------------
    {
        const int ml  = tid >> 1;                 // 0..127
        const int jl0 = (tid & 1) * 8;
        const int b   = brow0 + ml;
        const float xv = x_base[b * x_stride + x_off];
#pragma unroll
        for (int j = 0; j < 8; j++) {
            const int jl = jl0 + j;
            const int jh = nt * 16 + jl;
            const float zi = zs[ml * 68 +      jl] + xv * __ldg(&Wih[jh])        + __ldg(&bias[jh]);
            const float zf = zs[ml * 68 + 16 + jl] + xv * __ldg(&Wih[512 + jh])  + __ldg(&bias[512 + jh]);
            const float zg = zs[ml * 68 + 32 + jl] + xv * __ldg(&Wih[1024 + jh]) + __ldg(&bias[1024 + jh]);
            const float zo = zs[ml * 68 + 48 + jl] + xv * __ldg(&Wih[1536 + jh]) + __ldg(&bias[1536 + jh]);
            const int idx = b * H + jh;
            const float cn = sigf(zf) * g_c[idx] + sigf(zi) * tanhf(zg);
            g_c[idx] = cn;
            const float hv = sigf(zo) * tanhf(cn);
            const __nv_bfloat16 hh = __float2bfloat16_rn(hv);
            hhi_out[idx] = hh;
            hlo_out[idx] = __float2bfloat16_rn(hv - __bfloat162float(hh));
        }
    }
}

// ---------------- decoder output + feedback ---------------------------------
__global__ void __launch_bounds__(256)
dec_out_kernel(const __nv_bfloat16* __restrict__ hhi,
               const __nv_bfloat16* __restrict__ hlo,
               const float* __restrict__ linW,
               const float* __restrict__ linb,
               float* __restrict__ out, int t)
{
    const int b    = blockIdx.x * 8 + (threadIdx.x >> 5);
    const int lane = threadIdx.x & 31;
    const size_t base = (size_t)b * H;
    float s = 0.0f;
#pragma unroll
    for (int k = lane; k < H; k += 32) {
        float hv = __bfloat162float(hhi[base + k]) + __bfloat162float(hlo[base + k]);
        s = fmaf(hv, linW[k], s);
    }
#pragma unroll
    for (int o = 16; o; o >>= 1)
        s += __shfl_xor_sync(0xffffffffu, s, o);
    if (lane == 0) {
        const float v = s + linb[0];
        g_x[b] = v;
        out[b * TDEC + t] = v;
    }
}

// ---------------- launch ------------------------------------------------------
extern "C" void kernel_launch(void* const* d_in, const int* in_sizes, int n_in,
                              void* d_out, int out_size)
{
    (void)in_sizes; (void)n_in; (void)out_size;
    const float* inputs = (const float*)d_in[0];
    // d_in[1] = targets (unused: teacher_forcing_ratio == 0)
    const float* encWih = (const float*)d_in[2];
    const float* encWhh = (const float*)d_in[3];
    const float* encB   = (const float*)d_in[4];
    const float* decWih = (const float*)d_in[5];
    const float* decWhh = (const float*)d_in[6];
    const float* decB   = (const float*)d_in[7];
    const float* linW   = (const float*)d_in[8];
    const float* linB   = (const float*)d_in[9];
    float* out = (float*)d_out;

    cudaFuncSetAttribute(lstm_step_kernel,
                         cudaFuncAttributeMaxDynamicSharedMemorySize, SMEM_DYN);

    __nv_bfloat16 *hhi[2], *hlo[2], *whiE, *wloE, *whiD, *wloD;
    float* xp;
    cudaGetSymbolAddress((void**)&hhi[0], g_hhi0);
    cudaGetSymbolAddress((void**)&hhi[1], g_hhi1);
    cudaGetSymbolAddress((void**)&hlo[0], g_hlo0);
    cudaGetSymbolAddress((void**)&hlo[1], g_hlo1);
    cudaGetSymbolAddress((void**)&whiE, g_whi_e);
    cudaGetSymbolAddress((void**)&wloE, g_wlo_e);
    cudaGetSymbolAddress((void**)&whiD, g_whi_d);
    cudaGetSymbolAddress((void**)&wloD, g_wlo_d);
    cudaGetSymbolAddress((void**)&xp, g_x);

    pack_w_kernel<<<4096, 256>>>(encWhh, whiE, wloE);
    pack_w_kernel<<<4096, 256>>>(decWhh, whiD, wloD);
    zero_state_kernel<<<(B * H) / 256, 256>>>();

    const dim3 grid(32, 4);   // nt x mt = 128 CTAs

    int s = 0;
    for (int t = 0; t < TENC; t++, s++) {
        lstm_step_kernel<<<grid, NTHREADS, SMEM_DYN>>>(
            hhi[s & 1], hlo[s & 1], hhi[(s & 1) ^ 1], hlo[(s & 1) ^ 1],
            whiE, wloE, encWih, encB, inputs, TENC, t);
    }

    seed_x_kernel<<<2, 256>>>(inputs);

    for (int t = 0; t < TDEC; t++, s++) {
        lstm_step_kernel<<<grid, NTHREADS, SMEM_DYN>>>(
            hhi[s & 1], hlo[s & 1], hhi[(s & 1) ^ 1], hlo[(s & 1) ^ 1],
            whiD, wloD, decWih, decB, xp, 1, 0);
        dec_out_kernel<<<B / 8, 256>>>(hhi[(s & 1) ^ 1], hlo[(s & 1) ^ 1],
                                       linW, linB, out, t);
    }
}

// round 8
// speedup vs baseline: 2.5233x; 1.4064x over previous
#include <cuda_runtime.h>
#include <cuda_bf16.h>
#include <stdint.h>
#include <math.h>

#define B      512
#define H      512
#define TENC   512
#define TDEC   128
#define NTHREADS 256
#define NCHUNK 24                    // 3 split-parts * (512/64) K-chunks
#define NSTAGE 4
#define STAGE_BYTES 24576            // A 16KB + B 8KB per stage
#define SMEM_DYN (NSTAGE * STAGE_BYTES + 1024)

// ---------------- persistent device state (no allocation allowed) ----------
static __device__ __align__(16) __nv_bfloat16 g_hhi0[B * H];
static __device__ __align__(16) __nv_bfloat16 g_hhi1[B * H];
static __device__ __align__(16) __nv_bfloat16 g_hlo0[B * H];
static __device__ __align__(16) __nv_bfloat16 g_hlo1[B * H];
static __device__ float g_c[B * H];
static __device__ float g_x[B];
static __device__ __align__(16) __nv_bfloat16 g_whi_e[2048 * 512];
static __device__ __align__(16) __nv_bfloat16 g_wlo_e[2048 * 512];
static __device__ __align__(16) __nv_bfloat16 g_whi_d[2048 * 512];
static __device__ __align__(16) __nv_bfloat16 g_wlo_d[2048 * 512];

// ---------------- helpers ----------------------------------------------------
__device__ __forceinline__ uint32_t smem_u32(const void* p) {
    uint32_t a;
    asm("{ .reg .u64 t; cvta.to.shared.u64 t, %1; cvt.u32.u64 %0, t; }"
        : "=r"(a) : "l"(p));
    return a;
}

__device__ __forceinline__ void cp16(uint32_t dst, const void* src) {
    asm volatile("cp.async.cg.shared.global [%0], [%1], 16;"
                 :: "r"(dst), "l"(src));
}
__device__ __forceinline__ void cp_commit() {
    asm volatile("cp.async.commit_group;" ::: "memory");
}
__device__ __forceinline__ void cp_wait2() {
    asm volatile("cp.async.wait_group 2;" ::: "memory");
}

__device__ __forceinline__ void ldsm_x4(uint32_t& r0, uint32_t& r1,
                                        uint32_t& r2, uint32_t& r3,
                                        uint32_t addr) {
    asm volatile("ldmatrix.sync.aligned.m8n8.x4.shared.b16 {%0,%1,%2,%3}, [%4];"
                 : "=r"(r0), "=r"(r1), "=r"(r2), "=r"(r3) : "r"(addr));
}

__device__ __forceinline__ void mma_bf16(float* c, const uint32_t* a,
                                         uint32_t b0, uint32_t b1) {
    asm volatile(
        "mma.sync.aligned.m16n8k16.row.col.f32.bf16.bf16.f32 "
        "{%0,%1,%2,%3}, {%4,%5,%6,%7}, {%8,%9}, {%0,%1,%2,%3};"
        : "+f"(c[0]), "+f"(c[1]), "+f"(c[2]), "+f"(c[3])
        : "r"(a[0]), "r"(a[1]), "r"(a[2]), "r"(a[3]), "r"(b0), "r"(b1));
}

__device__ __forceinline__ float sigf(float x) {
    return 1.0f / (1.0f + __expf(-x));
}

// ---------------- prologue kernels -------------------------------------------
// Repack W (2048,512): packed row n' = nt*64 + g*16 + jl  <->  n = g*512 + nt*16 + jl
__global__ void pack_w_kernel(const float* __restrict__ W,
                              __nv_bfloat16* __restrict__ whi,
                              __nv_bfloat16* __restrict__ wlo) {
    int idx = blockIdx.x * 256 + threadIdx.x;    // n'*512 + k
    int np = idx >> 9, k = idx & 511;
    int nt = np >> 6, r = np & 63;
    int n = (r >> 4) * 512 + nt * 16 + (r & 15);
    float w = W[n * 512 + k];
    __nv_bfloat16 hi = __float2bfloat16_rn(w);
    whi[idx] = hi;
    wlo[idx] = __float2bfloat16_rn(w - __bfloat162float(hi));
}

__global__ void zero_state_kernel() {
    int i = blockIdx.x * 256 + threadIdx.x;
    if (i < B * H) {
        g_hhi0[i] = __float2bfloat16(0.0f);
        g_hlo0[i] = __float2bfloat16(0.0f);
        g_c[i] = 0.0f;
    }
}

__global__ void seed_x_kernel(const float* __restrict__ inputs) {
    int b = blockIdx.x * 256 + threadIdx.x;
    if (b < B) g_x[b] = inputs[b * TENC + (TENC - 1)];
}

// ---------------- fused LSTM step (HMMA + 4-stage cp.async pipeline) ---------
// CTA (nt, mt): batch rows [mt*128,+128), packed z-cols [nt*64,+64)
// (= 4 gates x 16 hidden units jh in [nt*16,+16)).
// Split-3 bf16: hh*Wh + hh*Wl + hl*Wh as one K=1536 accumulation.
__global__ void __launch_bounds__(NTHREADS, 1)
lstm_step_kernel(const __nv_bfloat16* __restrict__ hhi,
                 const __nv_bfloat16* __restrict__ hlo,
                 __nv_bfloat16* __restrict__ hhi_out,
                 __nv_bfloat16* __restrict__ hlo_out,
                 const __nv_bfloat16* __restrict__ whi,
                 const __nv_bfloat16* __restrict__ wlo,
                 const float* __restrict__ Wih,
                 const float* __restrict__ bias,
                 const float* __restrict__ x_base,
                 int x_stride, int x_off)
{
    extern __shared__ char dsmem[];
    uint32_t raw = smem_u32(dsmem);
    uint32_t sb  = (raw + 1023) & ~1023u;
    char* sp     = dsmem + (sb - raw);
    float* zs    = (float*)sp;       // 128 x 68 f32 (34.8KB), reuses stages 0-1

    const int tid  = threadIdx.x;
    const int wid  = tid >> 5;
    const int lane = tid & 31;
    const int wm   = wid >> 1;        // warp m-tile 0..3 (32 rows each)
    const int wn   = wid & 1;         // warp n-tile 0..1 (32 cols each)
    const int nt   = blockIdx.x;      // 0..31
    const int mt   = blockIdx.y;      // 0..3
    const int brow0 = mt * 128;

    // ---- global->smem staging mapping (16B per slot, SW128-style swizzle) --
    const int gr  = tid >> 3;                 // 0..31 (row step 32)
    const int gce = (tid & 7) * 8;            // element col (8 bf16 = 16B)
    uint32_t soA[4], soB[2];
#pragma unroll
    for (int i = 0; i < 4; i++) {
        int row = gr + 32 * i;
        soA[i] = (uint32_t)row * 128u + (((uint32_t)gce * 2) ^ (uint32_t)((row & 7) << 4));
    }
#pragma unroll
    for (int i = 0; i < 2; i++) {
        int row = gr + 32 * i;
        soB[i] = (uint32_t)row * 128u + (((uint32_t)gce * 2) ^ (uint32_t)((row & 7) << 4));
    }

    // ---- ldmatrix lane addressing (per warp) --------------------------------
    const int lrow = lane & 15;
    const uint32_t kb2 = (uint32_t)((lane >> 4) * 16);   // byte offset of k-half
    uint32_t aoff[2], axor[2], boff[2], bxor[2];
#pragma unroll
    for (int mi = 0; mi < 2; mi++) {
        int r = wm * 32 + mi * 16 + lrow;
        aoff[mi] = (uint32_t)r * 128u;
        axor[mi] = (uint32_t)((r & 7) << 4);
    }
#pragma unroll
    for (int nb = 0; nb < 2; nb++) {
        int r = wn * 32 + nb * 16 + lrow;
        boff[nb] = (uint32_t)r * 128u;
        bxor[nb] = (uint32_t)((r & 7) << 4);
    }

    float acc[2][4][4];
#pragma unroll
    for (int mi = 0; mi < 2; mi++)
#pragma unroll
        for (int ni = 0; ni < 4; ni++)
#pragma unroll
            for (int q = 0; q < 4; q++) acc[mi][ni][q] = 0.0f;

    // ---- issue helper --------------------------------------------------------
    auto issue_chunk = [&](int kc) {
        const int part = kc >> 3;             // 0: hh*wh, 1: hh*wl, 2: hl*wh
        const int koff = (kc & 7) * 64;
        const __nv_bfloat16* aS = (part < 2 ? hhi : hlo);
        const __nv_bfloat16* bS = (part == 1 ? wlo : whi);
        const uint32_t ab = sb + (uint32_t)(kc & (NSTAGE - 1)) * STAGE_BYTES;
        const uint32_t bb = ab + 16384u;
#pragma unroll
        for (int i = 0; i < 4; i++)
            cp16(ab + soA[i], aS + (size_t)(brow0 + gr + 32 * i) * 512 + koff + gce);
#pragma unroll
        for (int i = 0; i < 2; i++)
            cp16(bb + soB[i], bS + (size_t)(nt * 64 + gr + 32 * i) * 512 + koff + gce);
        cp_commit();
    };

    // ---- prologue: fill 3 stages ---------------------------------------------
    issue_chunk(0);
    issue_chunk(1);
    issue_chunk(2);

    // ---- main K loop ----------------------------------------------------------
    for (int k = 0; k < NCHUNK; k++) {
        cp_wait2();          // stage k complete (groups always advance 1/iter)
        __syncthreads();     // visible to all; all warps done with chunk k-1

        if (k + 3 < NCHUNK) issue_chunk(k + 3);
        else                cp_commit();      // keep group count advancing

        const uint32_t au = sb + (uint32_t)(k & (NSTAGE - 1)) * STAGE_BYTES;
        const uint32_t bu = au + 16384u;
#pragma unroll
        for (int s = 0; s < 4; s++) {
            const uint32_t kb = (uint32_t)(s * 32);    // k0*2 bytes
            uint32_t af[2][4];
#pragma unroll
            for (int mi = 0; mi < 2; mi++)
                ldsm_x4(af[mi][0], af[mi][1], af[mi][2], af[mi][3],
                        au + aoff[mi] + ((kb + kb2) ^ axor[mi]));
            uint32_t bq[4][2];
#pragma unroll
            for (int nb = 0; nb < 2; nb++) {
                uint32_t q0, q1, q2, q3;
                ldsm_x4(q0, q1, q2, q3,
                        bu + boff[nb] + ((kb + kb2) ^ bxor[nb]));
                bq[nb * 2 + 0][0] = q0; bq[nb * 2 + 0][1] = q2;
                bq[nb * 2 + 1][0] = q1; bq[nb * 2 + 1][1] = q3;
            }
#pragma unroll
            for (int mi = 0; mi < 2; mi++)
#pragma unroll
                for (int ni = 0; ni < 4; ni++)
                    mma_bf16(acc[mi][ni], af[mi], bq[ni][0], bq[ni][1]);
        }
    }
    __syncthreads();   // all compute done before zs overwrites stages 0-1

    // ---- accum -> smem z tile (stride 68 to dodge bank conflicts) -----------
    {
        const int g  = lane >> 2;
        const int t2 = (lane & 3) * 2;
#pragma unroll
        for (int mi = 0; mi < 2; mi++)
#pragma unroll
            for (int ni = 0; ni < 4; ni++) {
                const int row = wm * 32 + mi * 16 + g;
                const int col = wn * 32 + ni * 8 + t2;
                *(float2*)(zs + row * 68 + col) =
                    make_float2(acc[mi][ni][0], acc[mi][ni][1]);
                *(float2*)(zs + (row + 8) * 68 + col) =
                    make_float2(acc[mi][ni][2], acc[mi][ni][3]);
            }
    }
    __syncthreads();

    // ---- gate pass: thread handles 8 (b, jh) pairs ---------------------------
    {
        const int ml  = tid >> 1;                 // 0..127
        const int jl0 = (tid & 1) * 8;
        const int b   = brow0 + ml;
        const float xv = x_base[b * x_stride + x_off];
#pragma unroll
        for (int j = 0; j < 8; j++) {
            const int jl = jl0 + j;
            const int jh = nt * 16 + jl;
            const float zi = zs[ml * 68 +      jl] + xv * __ldg(&Wih[jh])        + __ldg(&bias[jh]);
            const float zf = zs[ml * 68 + 16 + jl] + xv * __ldg(&Wih[512 + jh])  + __ldg(&bias[512 + jh]);
            const float zg = zs[ml * 68 + 32 + jl] + xv * __ldg(&Wih[1024 + jh]) + __ldg(&bias[1024 + jh]);
            const float zo = zs[ml * 68 + 48 + jl] + xv * __ldg(&Wih[1536 + jh]) + __ldg(&bias[1536 + jh]);
            const int idx = b * H + jh;
            const float cn = sigf(zf) * g_c[idx] + sigf(zi) * tanhf(zg);
            g_c[idx] = cn;
            const float hv = sigf(zo) * tanhf(cn);
            const __nv_bfloat16 hh = __float2bfloat16_rn(hv);
            hhi_out[idx] = hh;
            hlo_out[idx] = __float2bfloat16_rn(hv - __bfloat162float(hh));
        }
    }
}

// ---------------- decoder output + feedback ---------------------------------
__global__ void __launch_bounds__(256)
dec_out_kernel(const __nv_bfloat16* __restrict__ hhi,
               const __nv_bfloat16* __restrict__ hlo,
               const float* __restrict__ linW,
               const float* __restrict__ linb,
               float* __restrict__ out, int t)
{
    const int b    = blockIdx.x * 8 + (threadIdx.x >> 5);
    const int lane = threadIdx.x & 31;
    const size_t base = (size_t)b * H;
    float s = 0.0f;
#pragma unroll
    for (int k = lane; k < H; k += 32) {
        float hv = __bfloat162float(hhi[base + k]) + __bfloat162float(hlo[base + k]);
        s = fmaf(hv, linW[k], s);
    }
#pragma unroll
    for (int o = 16; o; o >>= 1)
        s += __shfl_xor_sync(0xffffffffu, s, o);
    if (lane == 0) {
        const float v = s + linb[0];
        g_x[b] = v;
        out[b * TDEC + t] = v;
    }
}

// ---------------- launch ------------------------------------------------------
extern "C" void kernel_launch(void* const* d_in, const int* in_sizes, int n_in,
                              void* d_out, int out_size)
{
    (void)in_sizes; (void)n_in; (void)out_size;
    const float* inputs = (const float*)d_in[0];
    // d_in[1] = targets (unused: teacher_forcing_ratio == 0)
    const float* encWih = (const float*)d_in[2];
    const float* encWhh = (const float*)d_in[3];
    const float* encB   = (const float*)d_in[4];
    const float* decWih = (const float*)d_in[5];
    const float* decWhh = (const float*)d_in[6];
    const float* decB   = (const float*)d_in[7];
    const float* linW   = (const float*)d_in[8];
    const float* linB   = (const float*)d_in[9];
    float* out = (float*)d_out;

    cudaFuncSetAttribute(lstm_step_kernel,
                         cudaFuncAttributeMaxDynamicSharedMemorySize, SMEM_DYN);

    __nv_bfloat16 *hhi[2], *hlo[2], *whiE, *wloE, *whiD, *wloD;
    float* xp;
    cudaGetSymbolAddress((void**)&hhi[0], g_hhi0);
    cudaGetSymbolAddress((void**)&hhi[1], g_hhi1);
    cudaGetSymbolAddress((void**)&hlo[0], g_hlo0);
    cudaGetSymbolAddress((void**)&hlo[1], g_hlo1);
    cudaGetSymbolAddress((void**)&whiE, g_whi_e);
    cudaGetSymbolAddress((void**)&wloE, g_wlo_e);
    cudaGetSymbolAddress((void**)&whiD, g_whi_d);
    cudaGetSymbolAddress((void**)&wloD, g_wlo_d);
    cudaGetSymbolAddress((void**)&xp, g_x);

    pack_w_kernel<<<4096, 256>>>(encWhh, whiE, wloE);
    pack_w_kernel<<<4096, 256>>>(decWhh, whiD, wloD);
    zero_state_kernel<<<(B * H) / 256, 256>>>();

    const dim3 grid(32, 4);   // nt x mt = 128 CTAs

    int s = 0;
    for (int t = 0; t < TENC; t++, s++) {
        lstm_step_kernel<<<grid, NTHREADS, SMEM_DYN>>>(
            hhi[s & 1], hlo[s & 1], hhi[(s & 1) ^ 1], hlo[(s & 1) ^ 1],
            whiE, wloE, encWih, encB, inputs, TENC, t);
    }

    seed_x_kernel<<<2, 256>>>(inputs);

    for (int t = 0; t < TDEC; t++, s++) {
        lstm_step_kernel<<<grid, NTHREADS, SMEM_DYN>>>(
            hhi[s & 1], hlo[s & 1], hhi[(s & 1) ^ 1], hlo[(s & 1) ^ 1],
            whiD, wloD, decWih, decB, xp, 1, 0);
        dec_out_kernel<<<B / 8, 256>>>(hhi[(s & 1) ^ 1], hlo[(s & 1) ^ 1],
                                       linW, linB, out, t);
    }
}